// round 15
// baseline (speedup 1.0000x reference)
#include <cuda_runtime.h>
#include <cuda_fp16.h>
#include <cstdint>

#define RDIM 128
#define CDIM 384
#define EDIM 768
#define HDIM 12
#define DDIM 64
#define MDIM (RDIM * CDIM)   // 49152

// GEMM tiling: CTA 128x128, 8 warps (2x4), warp tile 64x32, BK=64, 3-stage pipe
#define BK 64
#define GP 72                              // fp16/row (144B), conflict-free
#define MTX (128 * GP * 2)                 // 18432 B per matrix tile
#define GBUF (2 * MTX)                     // 36864 (A, B) per stage
#define NSTAGE 3

// attention smem map (bytes): q, k, v each 128x64 fp16 @ pitch PA
#define PA 72      // rows: 144B
#define AQ  0
#define AK  18432
#define AV  36864
#define ABM 55296              /* mask bitmap (4 x u32) */
#define ATOT (ABM + 16)

// ---------------- device scratch (allocation-free rule) ----------------
__device__ __half g_a[(size_t)MDIM * EDIM];      // A (x, then ctx), single fp16
__device__ __half g_w[(size_t)4 * EDIM * EDIM];  // packed wq|wk|wv|wo
__device__ float g_bias[4 * EDIM];
__device__ __half g_q[(size_t)MDIM * EDIM];      // [c][h][i][d]
__device__ __half g_k[(size_t)MDIM * EDIM];
__device__ __half g_v[(size_t)MDIM * EDIM];

// ---------------- helpers ----------------
__device__ __forceinline__ uint32_t smem_to_u32(const void* p) {
    uint32_t a;
    asm("{ .reg .u64 t; cvta.to.shared.u64 t, %1; cvt.u32.u64 %0, t; }"
        : "=r"(a) : "l"(p));
    return a;
}
__device__ __forceinline__ void cp16(uint32_t dst, const void* src) {
    asm volatile("cp.async.cg.shared.global [%0], [%1], 16;"
                 :: "r"(dst), "l"(src) : "memory");
}
__device__ __forceinline__ void cp_commit() {
    asm volatile("cp.async.commit_group;" ::: "memory");
}
__device__ __forceinline__ void cp_wait0() {
    asm volatile("cp.async.wait_group 0;" ::: "memory");
}
__device__ __forceinline__ void cp_wait1() {
    asm volatile("cp.async.wait_group 1;" ::: "memory");
}
__device__ __forceinline__ void ldmx4(uint32_t (&r)[4], uint32_t addr) {
    asm volatile("ldmatrix.sync.aligned.m8n8.x4.shared.b16 {%0,%1,%2,%3}, [%4];"
                 : "=r"(r[0]), "=r"(r[1]), "=r"(r[2]), "=r"(r[3]) : "r"(addr));
}
__device__ __forceinline__ void ldmx4t(uint32_t (&r)[4], uint32_t addr) {
    asm volatile("ldmatrix.sync.aligned.m8n8.x4.trans.shared.b16 {%0,%1,%2,%3}, [%4];"
                 : "=r"(r[0]), "=r"(r[1]), "=r"(r[2]), "=r"(r[3]) : "r"(addr));
}
__device__ __forceinline__ void mma16816(float (&d)[4], const uint32_t (&a)[4],
                                         uint32_t b0, uint32_t b1) {
    asm volatile(
        "mma.sync.aligned.m16n8k16.row.col.f32.f16.f16.f32 "
        "{%0,%1,%2,%3}, {%4,%5,%6,%7}, {%8,%9}, {%0,%1,%2,%3};"
        : "+f"(d[0]), "+f"(d[1]), "+f"(d[2]), "+f"(d[3])
        : "r"(a[0]), "r"(a[1]), "r"(a[2]), "r"(a[3]), "r"(b0), "r"(b1));
}
__device__ __forceinline__ uint32_t packh(float a, float b) {
    __half2 p(__float2half_rn(a), __float2half_rn(b));
    return *(uint32_t*)&p;
}

// ---------------- merged conversion kernel ----------------
// blocks [0, 2304): weights+bias; blocks [2304, 11520): x (float4 granules)
__global__ void conv_all(const float* __restrict__ x,
                         const float* __restrict__ wq, const float* __restrict__ wk,
                         const float* __restrict__ wv, const float* __restrict__ wo,
                         const float* __restrict__ bq, const float* __restrict__ bk,
                         const float* __restrict__ bv, const float* __restrict__ bo)
{
    if (blockIdx.x < 2304) {
        const size_t WSZ = (size_t)EDIM * EDIM;
        size_t i = (size_t)blockIdx.x * blockDim.x + threadIdx.x;  // < 4*WSZ exact
        int sel = (int)(i / WSZ);
        size_t off = i - (size_t)sel * WSZ;
        const float* w = (sel == 0) ? wq : (sel == 1) ? wk : (sel == 2) ? wv : wo;
        g_w[i] = __float2half_rn(w[off]);
        if (i < 4 * EDIM) {
            int s = (int)(i / EDIM), r = (int)(i % EDIM);
            const float* b = (s == 0) ? bq : (s == 1) ? bk : (s == 2) ? bv : bo;
            g_bias[i] = b[r];
        }
    } else {
        int i = (blockIdx.x - 2304) * blockDim.x + threadIdx.x;    // < MDIM*EDIM/4 exact
        float4 v = ((const float4*)x)[i];
        size_t o = (size_t)i * 4;
        *(__half2*)(g_a + o)     = __half2(__float2half_rn(v.x), __float2half_rn(v.y));
        *(__half2*)(g_a + o + 2) = __half2(__float2half_rn(v.z), __float2half_rn(v.w));
    }
}

// ---------------- fp16 HMMA GEMM (single product, BK=64, 3-stage cp.async) ----------------
__global__ __launch_bounds__(256, 2)
void gemm_tc(int n_off, int mode, float* __restrict__ outp)
{
    extern __shared__ char smdyn[];
    const uint32_t smb = smem_to_u32(smdyn);
    const int t = threadIdx.x;
    const int wid = t >> 5, lane = t & 31;
    const int wm = wid & 1, wn = wid >> 1;           // 2x4 warp grid
    const int bm = blockIdx.y * 128;
    const int nb = n_off + blockIdx.x * 128;

    const __half* srcA = g_a + (size_t)bm * EDIM;
    const __half* srcB = g_w + (size_t)nb * EDIM;

    float acc[4][4][4];
#pragma unroll
    for (int mi = 0; mi < 4; ++mi)
#pragma unroll
        for (int ni = 0; ni < 4; ++ni)
#pragma unroll
            for (int e = 0; e < 4; ++e) acc[mi][ni][e] = 0.0f;

    const int lrow8 = (lane & 7) + ((lane >> 3) & 1) * 8;
    const int lkoff = (lane >> 4) * 8;
    const int NC = EDIM / BK;  // 12

    // prefetch chunks 0 and 1 (two commit groups)
#pragma unroll
    for (int pf = 0; pf < 2; ++pf) {
        const uint32_t bufn = pf * GBUF;
#pragma unroll
        for (int kk = 0; kk < 4; ++kk) {
            const int id = t + kk * 256;
            const int r = id >> 3, cl = id & 7;
            const uint32_t d = smb + bufn + (uint32_t)(r * (GP * 2) + cl * 16);
            const int s = r * EDIM + pf * BK + cl * 8;
            cp16(d, srcA + s);
            cp16(d + MTX, srcB + s);
        }
        cp_commit();
    }

    int bufc = 0;   // buffer index of current chunk
#pragma unroll 1
    for (int ch = 0; ch < NC; ++ch) {
        if (ch + 1 < NC) cp_wait1(); else cp_wait0();
        __syncthreads();
        if (ch + 2 < NC) {
            const int bufp = (bufc + 2 >= NSTAGE) ? bufc + 2 - NSTAGE : bufc + 2;
            const uint32_t bufn = (uint32_t)bufp * GBUF;
#pragma unroll
            for (int kk = 0; kk < 4; ++kk) {
                const int id = t + kk * 256;
                const int r = id >> 3, cl = id & 7;
                const uint32_t d = smb + bufn + (uint32_t)(r * (GP * 2) + cl * 16);
                const int s = r * EDIM + (ch + 2) * BK + cl * 8;
                cp16(d, srcA + s);
                cp16(d + MTX, srcB + s);
            }
            cp_commit();
        }
        const uint32_t buf = smb + (uint32_t)bufc * GBUF;
        const uint32_t aA = buf + (uint32_t)((wm * 64 + lrow8) * (GP * 2));
        const uint32_t aB = buf + MTX + (uint32_t)((wn * 32 + lrow8) * (GP * 2));
#pragma unroll
        for (int ks = 0; ks < 4; ++ks) {
            const uint32_t kbyte = (uint32_t)((ks * 16 + lkoff) * 2);
            uint32_t bfr[2][4];
#pragma unroll
            for (int ng = 0; ng < 2; ++ng)
                ldmx4(bfr[ng], aB + (uint32_t)(ng * 16 * GP * 2) + kbyte);
#pragma unroll
            for (int mi = 0; mi < 4; ++mi) {
                uint32_t af[4];
                ldmx4(af, aA + (uint32_t)(mi * 16 * GP * 2) + kbyte);
#pragma unroll
                for (int ni = 0; ni < 4; ++ni) {
                    const int ng = ni >> 1, lo = ni & 1;
                    mma16816(acc[mi][ni], af, bfr[ng][lo], bfr[ng][lo + 2]);
                }
            }
        }
        bufc = (bufc + 1 >= NSTAGE) ? 0 : bufc + 1;
    }

    // epilogue
    const int r0 = bm + wm * 64 + (lane >> 2);
    const int cbase = nb + wn * 32 + (lane & 3) * 2;
#pragma unroll
    for (int mi = 0; mi < 4; ++mi) {
#pragma unroll
        for (int half = 0; half < 2; ++half) {
            const int m = r0 + mi * 16 + half * 8;
            const int i_ = m / CDIM, c_ = m % CDIM;
#pragma unroll
            for (int ni = 0; ni < 4; ++ni) {
                const int ng = cbase + ni * 8;
                float ox = acc[mi][ni][half * 2 + 0] + g_bias[ng + 0];
                float oy = acc[mi][ni][half * 2 + 1] + g_bias[ng + 1];
                if (mode == 0) {
                    const int sel = ng / EDIM, f = ng % EDIM, h = f >> 6, d = f & 63;
                    if (sel == 0) { ox *= 0.125f; oy *= 0.125f; }
                    __half* dst = (sel == 0) ? g_q : (sel == 1) ? g_k : g_v;
                    const size_t off = (((size_t)c_ * HDIM + h) * RDIM + i_) * DDIM + d;
                    *(__half2*)(dst + off) =
                        __half2(__float2half_rn(ox), __float2half_rn(oy));
                } else {
                    float2 o; o.x = ox; o.y = oy;
                    *(float2*)(outp + (size_t)m * EDIM + (ng - 3 * EDIM)) = o;
                }
            }
        }
    }
}

// ---------------- register-flash fp16 HMMA attention (1 head/CTA, 2 CTAs/SM) ----------------
// PV uses ldmatrix.trans directly on V [j][d] — no smem transpose, no extra barriers.
__global__ __launch_bounds__(256, 2)
void attn_tc(const unsigned char* __restrict__ mask, float* __restrict__ probs)
{
    extern __shared__ char sm[];
    const uint32_t smb = smem_to_u32(sm);
    const int c = blockIdx.x, h = blockIdx.y;
    const int t = threadIdx.x, wid = t >> 5, lane = t & 31;

    // ---- loads: q, k, v, all [128][64] fp16 ----
    {
        const size_t gb = ((size_t)c * HDIM + h) * (RDIM * DDIM);
        const __half* sq[3] = { g_q + gb, g_k + gb, g_v + gb };
        const uint32_t qo[3] = { AQ, AK, AV };
#pragma unroll
        for (int m = 0; m < 3; ++m)
#pragma unroll
            for (int k = 0; k < 4; ++k) {
                const int id = t + k * 256;
                const int r = id >> 3, cl = id & 7;
                cp16(smb + qo[m] + (uint32_t)(r * (PA * 2) + cl * 16),
                     sq[m] + (size_t)r * DDIM + cl * 8);
            }
    }
    cp_commit();

    // mask bitmap
    uint32_t* bmw = (uint32_t*)(sm + ABM);
    if (t < 4) bmw[t] = 0;
    __syncthreads();
    if (t < RDIM && mask[(size_t)t * CDIM + c]) atomicOr(&bmw[t >> 5], 1u << (t & 31));
    cp_wait0();
    __syncthreads();
    const uint32_t mb[4] = { bmw[0], bmw[1], bmw[2], bmw[3] };
    const bool any_mask = (mb[0] | mb[1] | mb[2] | mb[3]) != 0;

    const int rw = wid;                       // warp owns rows [16rw, 16rw+16)
    const int lrow8 = (lane & 7) + ((lane >> 3) & 1) * 8;
    const int lkoff = (lane >> 4) * 8;

    // ---- S = Q K^T : warp tile 16(m) x 128(n), k=64, single product ----
    float sacc[16][4];
#pragma unroll
    for (int ni = 0; ni < 16; ++ni)
#pragma unroll
        for (int e = 0; e < 4; ++e) sacc[ni][e] = 0.0f;

    const uint32_t qb = smb + AQ + (uint32_t)((rw * 16 + lrow8) * (PA * 2));
    const uint32_t kbse = smb + AK + (uint32_t)(lrow8 * (PA * 2));
#pragma unroll
    for (int ks = 0; ks < 4; ++ks) {
        const uint32_t ko = (uint32_t)((ks * 16 + lkoff) * 2);
        uint32_t qf[4];
        ldmx4(qf, qb + ko);
#pragma unroll
        for (int nh = 0; nh < 2; ++nh) {
            uint32_t kf[4][4];
#pragma unroll
            for (int nb8 = 0; nb8 < 4; ++nb8)
                ldmx4(kf[nb8], kbse + (uint32_t)((nh * 64 + nb8 * 16) * (PA * 2)) + ko);
#pragma unroll
            for (int ni = 0; ni < 8; ++ni) {
                const int g = ni >> 1, lo = ni & 1, idx = nh * 8 + ni;
                mma16816(sacc[idx], qf, kf[g][lo], kf[g][lo + 2]);
            }
        }
    }

    // ---- mask + warp-local softmax ----
    if (any_mask) {
#pragma unroll
        for (int ni = 0; ni < 16; ++ni) {
            const uint32_t w = mb[ni >> 2];
            const int b0 = (ni & 3) * 8 + (lane & 3) * 2;
            if ((w >> b0) & 1)       { sacc[ni][0] = -10000.0f; sacc[ni][2] = -10000.0f; }
            if ((w >> (b0 + 1)) & 1) { sacc[ni][1] = -10000.0f; sacc[ni][3] = -10000.0f; }
        }
    }
    float mx0 = -3.0e38f, mx1 = -3.0e38f;
#pragma unroll
    for (int ni = 0; ni < 16; ++ni) {
        mx0 = fmaxf(mx0, fmaxf(sacc[ni][0], sacc[ni][1]));
        mx1 = fmaxf(mx1, fmaxf(sacc[ni][2], sacc[ni][3]));
    }
    mx0 = fmaxf(mx0, __shfl_xor_sync(0xffffffffu, mx0, 1));
    mx0 = fmaxf(mx0, __shfl_xor_sync(0xffffffffu, mx0, 2));
    mx1 = fmaxf(mx1, __shfl_xor_sync(0xffffffffu, mx1, 1));
    mx1 = fmaxf(mx1, __shfl_xor_sync(0xffffffffu, mx1, 2));

    float s0 = 0.0f, s1 = 0.0f;
#pragma unroll
    for (int ni = 0; ni < 16; ++ni) {
        sacc[ni][0] = __expf(sacc[ni][0] - mx0);
        sacc[ni][1] = __expf(sacc[ni][1] - mx0);
        sacc[ni][2] = __expf(sacc[ni][2] - mx1);
        sacc[ni][3] = __expf(sacc[ni][3] - mx1);
        s0 += sacc[ni][0] + sacc[ni][1];
        s1 += sacc[ni][2] + sacc[ni][3];
    }
    s0 += __shfl_xor_sync(0xffffffffu, s0, 1);
    s0 += __shfl_xor_sync(0xffffffffu, s0, 2);
    s1 += __shfl_xor_sync(0xffffffffu, s1, 1);
    s1 += __shfl_xor_sync(0xffffffffu, s1, 2);
    const float inv0 = 1.0f / s0, inv1 = 1.0f / s1;

    // ---- probs (normalized fp32) straight from registers ----
    {
        const int r0 = rw * 16 + (lane >> 2);
        float* pb = probs + (((size_t)h * CDIM + c) * RDIM + r0) * RDIM + (lane & 3) * 2;
#pragma unroll
        for (int ni = 0; ni < 16; ++ni) {
            float2 a; a.x = sacc[ni][0] * inv0; a.y = sacc[ni][1] * inv0;
            float2 b; b.x = sacc[ni][2] * inv1; b.y = sacc[ni][3] * inv1;
            *(float2*)(pb + ni * 8) = a;
            *(float2*)(pb + 8 * RDIM + ni * 8) = b;
        }
    }

    // ---- pack unnormalized P -> fp16 A-fragments ----
    uint32_t ph0[16], ph1[16];
#pragma unroll
    for (int ni = 0; ni < 16; ++ni) {
        ph0[ni] = packh(sacc[ni][0], sacc[ni][1]);
        ph1[ni] = packh(sacc[ni][2], sacc[ni][3]);
    }

    // ---- ctx = P V : warp tile 16(m) x 64(n), k=128, V via ldmatrix.trans ----
    const int trow = (lane & 7) + ((lane >> 4) << 3);
    const int tcol = ((lane >> 3) & 1) * 8;
    const uint32_t vb = smb + AV + (uint32_t)(trow * (PA * 2) + tcol * 2);

    float cacc[8][4];
#pragma unroll
    for (int ni = 0; ni < 8; ++ni)
#pragma unroll
        for (int e = 0; e < 4; ++e) cacc[ni][e] = 0.0f;

#pragma unroll
    for (int kb = 0; kb < 8; ++kb) {
        const uint32_t krow = (uint32_t)(kb * 16 * (PA * 2));
        const uint32_t a_h[4] = { ph0[2 * kb], ph1[2 * kb], ph0[2 * kb + 1], ph1[2 * kb + 1] };
#pragma unroll
        for (int vh2 = 0; vh2 < 2; ++vh2) {
            uint32_t vf[2][4];
#pragma unroll
            for (int nb8 = 0; nb8 < 2; ++nb8)
                ldmx4t(vf[nb8], vb + krow + (uint32_t)((vh2 * 32 + nb8 * 16) * 2));
#pragma unroll
            for (int nl = 0; nl < 4; ++nl) {
                const int g = nl >> 1, lo = nl & 1, idx = vh2 * 4 + nl;
                mma16816(cacc[idx], a_h, vf[g][lo], vf[g][lo + 2]);
            }
        }
    }

    // ---- ctx epilogue (normalize, single fp16, feed out-projection) ----
    {
        const int r0 = rw * 16 + (lane >> 2);
#pragma unroll
        for (int ni = 0; ni < 8; ++ni) {
            const int d = ni * 8 + (lane & 3) * 2;
            const size_t ob0 = ((size_t)r0 * CDIM + c) * EDIM + h * DDIM + d;
            const size_t ob1 = ((size_t)(r0 + 8) * CDIM + c) * EDIM + h * DDIM + d;
            *(__half2*)(g_a + ob0) = __half2(__float2half_rn(cacc[ni][0] * inv0),
                                             __float2half_rn(cacc[ni][1] * inv0));
            *(__half2*)(g_a + ob1) = __half2(__float2half_rn(cacc[ni][2] * inv1),
                                             __float2half_rn(cacc[ni][3] * inv1));
        }
    }
}

// ---------------------------------------------------------------------------
extern "C" void kernel_launch(void* const* d_in, const int* in_sizes, int n_in,
                              void* d_out, int out_size)
{
    const float* x  = (const float*)d_in[0];
    const unsigned char* mask = (const unsigned char*)d_in[2];
    const float* wq = (const float*)d_in[3];
    const float* bq = (const float*)d_in[4];
    const float* wk = (const float*)d_in[5];
    const float* bk = (const float*)d_in[6];
    const float* wv = (const float*)d_in[7];
    const float* bv = (const float*)d_in[8];
    const float* wo = (const float*)d_in[9];
    const float* bo = (const float*)d_in[10];

    float* out   = (float*)d_out;                    // (R, C, 1, E)
    float* probs = out + (size_t)MDIM * EDIM;        // (H, C, 1, R, R)

    const int gemm_smem = NSTAGE * GBUF;             // 110592
    cudaFuncSetAttribute(gemm_tc, cudaFuncAttributeMaxDynamicSharedMemorySize, gemm_smem);
    cudaFuncSetAttribute(attn_tc, cudaFuncAttributeMaxDynamicSharedMemorySize, ATOT);

    conv_all<<<11520, 1024>>>(x, wq, wk, wv, wo, bq, bk, bv, bo);
    gemm_tc<<<dim3(18, MDIM / 128), 256, gemm_smem>>>(0, 0, out);        // qkv
    attn_tc<<<dim3(CDIM, HDIM), 256, ATOT>>>(mask, probs);
    gemm_tc<<<dim3(6, MDIM / 128), 256, gemm_smem>>>(3 * EDIM, 1, out);  // out proj
}

// round 16
// speedup vs baseline: 1.0232x; 1.0232x over previous
#include <cuda_runtime.h>
#include <cuda_fp16.h>
#include <cstdint>

#define RDIM 128
#define CDIM 384
#define EDIM 768
#define HDIM 12
#define DDIM 64
#define MDIM (RDIM * CDIM)   // 49152

// GEMM tiling: CTA 128x128, 8 warps (2x4), warp tile 64x32, BK=64, double buffer
#define BK 64
#define GP 72                              // fp16/row (144B), conflict-free
#define MTX (128 * GP * 2)                 // 18432 B per matrix tile
#define GBUF (2 * MTX)                     // 36864 (A, B)

// attention smem map (bytes): q, k, v each 128x64 fp16 @ pitch PA
#define PA 72      // rows: 144B
#define AQ  0
#define AK  18432
#define AV  36864
#define ABM 55296              /* mask bitmap (4 x u32) */
#define ATOT (ABM + 16)

// ---------------- device scratch (allocation-free rule) ----------------
__device__ __half g_a[(size_t)MDIM * EDIM];      // A (x, then ctx), single fp16
__device__ __half g_w[(size_t)4 * EDIM * EDIM];  // packed wq|wk|wv|wo
__device__ float g_bias[4 * EDIM];
__device__ __half g_q[(size_t)MDIM * EDIM];      // [c][h][i][d]
__device__ __half g_k[(size_t)MDIM * EDIM];
__device__ __half g_v[(size_t)MDIM * EDIM];

// ---------------- helpers ----------------
__device__ __forceinline__ uint32_t smem_to_u32(const void* p) {
    uint32_t a;
    asm("{ .reg .u64 t; cvta.to.shared.u64 t, %1; cvt.u32.u64 %0, t; }"
        : "=r"(a) : "l"(p));
    return a;
}
__device__ __forceinline__ void cp16(uint32_t dst, const void* src) {
    asm volatile("cp.async.cg.shared.global [%0], [%1], 16;"
                 :: "r"(dst), "l"(src) : "memory");
}
__device__ __forceinline__ void cp_commit() {
    asm volatile("cp.async.commit_group;" ::: "memory");
}
__device__ __forceinline__ void cp_wait0() {
    asm volatile("cp.async.wait_group 0;" ::: "memory");
}
__device__ __forceinline__ void ldmx4(uint32_t (&r)[4], uint32_t addr) {
    asm volatile("ldmatrix.sync.aligned.m8n8.x4.shared.b16 {%0,%1,%2,%3}, [%4];"
                 : "=r"(r[0]), "=r"(r[1]), "=r"(r[2]), "=r"(r[3]) : "r"(addr));
}
__device__ __forceinline__ void ldmx4t(uint32_t (&r)[4], uint32_t addr) {
    asm volatile("ldmatrix.sync.aligned.m8n8.x4.trans.shared.b16 {%0,%1,%2,%3}, [%4];"
                 : "=r"(r[0]), "=r"(r[1]), "=r"(r[2]), "=r"(r[3]) : "r"(addr));
}
__device__ __forceinline__ void mma16816(float (&d)[4], const uint32_t (&a)[4],
                                         uint32_t b0, uint32_t b1) {
    asm volatile(
        "mma.sync.aligned.m16n8k16.row.col.f32.f16.f16.f32 "
        "{%0,%1,%2,%3}, {%4,%5,%6,%7}, {%8,%9}, {%0,%1,%2,%3};"
        : "+f"(d[0]), "+f"(d[1]), "+f"(d[2]), "+f"(d[3])
        : "r"(a[0]), "r"(a[1]), "r"(a[2]), "r"(a[3]), "r"(b0), "r"(b1));
}
__device__ __forceinline__ uint32_t packh(float a, float b) {
    __half2 p(__float2half_rn(a), __float2half_rn(b));
    return *(uint32_t*)&p;
}

// ---------------- merged conversion kernel ----------------
// blocks [0, 2304): weights+bias; blocks [2304, 11520): x (float4 granules)
__global__ void conv_all(const float* __restrict__ x,
                         const float* __restrict__ wq, const float* __restrict__ wk,
                         const float* __restrict__ wv, const float* __restrict__ wo,
                         const float* __restrict__ bq, const float* __restrict__ bk,
                         const float* __restrict__ bv, const float* __restrict__ bo)
{
    if (blockIdx.x < 2304) {
        const size_t WSZ = (size_t)EDIM * EDIM;
        size_t i = (size_t)blockIdx.x * blockDim.x + threadIdx.x;  // < 4*WSZ exact
        int sel = (int)(i / WSZ);
        size_t off = i - (size_t)sel * WSZ;
        const float* w = (sel == 0) ? wq : (sel == 1) ? wk : (sel == 2) ? wv : wo;
        g_w[i] = __float2half_rn(w[off]);
        if (i < 4 * EDIM) {
            int s = (int)(i / EDIM), r = (int)(i % EDIM);
            const float* b = (s == 0) ? bq : (s == 1) ? bk : (s == 2) ? bv : bo;
            g_bias[i] = b[r];
        }
    } else {
        int i = (blockIdx.x - 2304) * blockDim.x + threadIdx.x;    // < MDIM*EDIM/4 exact
        float4 v = ((const float4*)x)[i];
        size_t o = (size_t)i * 4;
        *(__half2*)(g_a + o)     = __half2(__float2half_rn(v.x), __float2half_rn(v.y));
        *(__half2*)(g_a + o + 2) = __half2(__float2half_rn(v.z), __float2half_rn(v.w));
    }
}

// ---------------- fp16 HMMA GEMM (single product, BK=64, double buffer) ----------------
__global__ __launch_bounds__(256, 2)
void gemm_tc(int n_off, int mode, float* __restrict__ outp)
{
    extern __shared__ char smdyn[];
    const uint32_t smb = smem_to_u32(smdyn);
    const int t = threadIdx.x;
    const int wid = t >> 5, lane = t & 31;
    const int wm = wid & 1, wn = wid >> 1;           // 2x4 warp grid
    const int bm = blockIdx.y * 128;
    const int nb = n_off + blockIdx.x * 128;

    const __half* srcA = g_a + (size_t)bm * EDIM;
    const __half* srcB = g_w + (size_t)nb * EDIM;

    float acc[4][4][4];
#pragma unroll
    for (int mi = 0; mi < 4; ++mi)
#pragma unroll
        for (int ni = 0; ni < 4; ++ni)
#pragma unroll
            for (int e = 0; e < 4; ++e) acc[mi][ni][e] = 0.0f;

    const int lrow8 = (lane & 7) + ((lane >> 3) & 1) * 8;
    const int lkoff = (lane >> 4) * 8;

    // prefetch chunk 0: per matrix 1024 x 16B; 256 threads x 4
    {
#pragma unroll
        for (int kk = 0; kk < 4; ++kk) {
            const int id = t + kk * 256;
            const int r = id >> 3, cl = id & 7;
            const uint32_t d = smb + (uint32_t)(r * (GP * 2) + cl * 16);
            const int s = r * EDIM + cl * 8;
            cp16(d, srcA + s);
            cp16(d + MTX, srcB + s);
        }
        cp_commit();
    }

    const int NC = EDIM / BK;  // 12
#pragma unroll 1
    for (int ch = 0; ch < NC; ++ch) {
        cp_wait0();
        __syncthreads();
        if (ch + 1 < NC) {
            const uint32_t bufn = ((ch + 1) & 1) * GBUF;
#pragma unroll
            for (int kk = 0; kk < 4; ++kk) {
                const int id = t + kk * 256;
                const int r = id >> 3, cl = id & 7;
                const uint32_t d = smb + bufn + (uint32_t)(r * (GP * 2) + cl * 16);
                const int s = r * EDIM + (ch + 1) * BK + cl * 8;
                cp16(d, srcA + s);
                cp16(d + MTX, srcB + s);
            }
            cp_commit();
        }
        const uint32_t buf = smb + (ch & 1) * GBUF;
        const uint32_t aA = buf + (uint32_t)((wm * 64 + lrow8) * (GP * 2));
        const uint32_t aB = buf + MTX + (uint32_t)((wn * 32 + lrow8) * (GP * 2));
#pragma unroll
        for (int ks = 0; ks < 4; ++ks) {
            const uint32_t kbyte = (uint32_t)((ks * 16 + lkoff) * 2);
            uint32_t bfr[2][4];
#pragma unroll
            for (int ng = 0; ng < 2; ++ng)
                ldmx4(bfr[ng], aB + (uint32_t)(ng * 16 * GP * 2) + kbyte);
#pragma unroll
            for (int mi = 0; mi < 4; ++mi) {
                uint32_t af[4];
                ldmx4(af, aA + (uint32_t)(mi * 16 * GP * 2) + kbyte);
#pragma unroll
                for (int ni = 0; ni < 4; ++ni) {
                    const int ng = ni >> 1, lo = ni & 1;
                    mma16816(acc[mi][ni], af, bfr[ng][lo], bfr[ng][lo + 2]);
                }
            }
        }
    }

    // epilogue
    const int r0 = bm + wm * 64 + (lane >> 2);
    const int cbase = nb + wn * 32 + (lane & 3) * 2;
#pragma unroll
    for (int mi = 0; mi < 4; ++mi) {
#pragma unroll
        for (int half = 0; half < 2; ++half) {
            const int m = r0 + mi * 16 + half * 8;
            const int i_ = m / CDIM, c_ = m % CDIM;
#pragma unroll
            for (int ni = 0; ni < 4; ++ni) {
                const int ng = cbase + ni * 8;
                float ox = acc[mi][ni][half * 2 + 0] + g_bias[ng + 0];
                float oy = acc[mi][ni][half * 2 + 1] + g_bias[ng + 1];
                if (mode == 0) {
                    const int sel = ng / EDIM, f = ng % EDIM, h = f >> 6, d = f & 63;
                    if (sel == 0) { ox *= 0.125f; oy *= 0.125f; }
                    __half* dst = (sel == 0) ? g_q : (sel == 1) ? g_k : g_v;
                    const size_t off = (((size_t)c_ * HDIM + h) * RDIM + i_) * DDIM + d;
                    *(__half2*)(dst + off) =
                        __half2(__float2half_rn(ox), __float2half_rn(oy));
                } else {
                    float2 o; o.x = ox; o.y = oy;
                    *(float2*)(outp + (size_t)m * EDIM + (ng - 3 * EDIM)) = o;
                }
            }
        }
    }
}

// ---------------- register-flash fp16 HMMA attention (1 head/CTA, 2 CTAs/SM) ----------------
__global__ __launch_bounds__(256, 2)
void attn_tc(const unsigned char* __restrict__ mask, float* __restrict__ probs)
{
    extern __shared__ char sm[];
    const uint32_t smb = smem_to_u32(sm);
    const int c = blockIdx.x, h = blockIdx.y;
    const int t = threadIdx.x, wid = t >> 5, lane = t & 31;

    // ---- loads: q, k, v, all [128][64] fp16 ----
    {
        const size_t gb = ((size_t)c * HDIM + h) * (RDIM * DDIM);
        const __half* sq[3] = { g_q + gb, g_k + gb, g_v + gb };
        const uint32_t qo[3] = { AQ, AK, AV };
#pragma unroll
        for (int m = 0; m < 3; ++m)
#pragma unroll
            for (int k = 0; k < 4; ++k) {
                const int id = t + k * 256;
                const int r = id >> 3, cl = id & 7;
                cp16(smb + qo[m] + (uint32_t)(r * (PA * 2) + cl * 16),
                     sq[m] + (size_t)r * DDIM + cl * 8);
            }
    }
    cp_commit();

    // mask bitmap
    uint32_t* bmw = (uint32_t*)(sm + ABM);
    if (t < 4) bmw[t] = 0;
    __syncthreads();
    if (t < RDIM && mask[(size_t)t * CDIM + c]) atomicOr(&bmw[t >> 5], 1u << (t & 31));
    cp_wait0();
    __syncthreads();
    const uint32_t mb[4] = { bmw[0], bmw[1], bmw[2], bmw[3] };
    const bool any_mask = (mb[0] | mb[1] | mb[2] | mb[3]) != 0;

    const int rw = wid;                       // warp owns rows [16rw, 16rw+16)
    const int lrow8 = (lane & 7) + ((lane >> 3) & 1) * 8;
    const int lkoff = (lane >> 4) * 8;

    // ---- S = Q K^T : warp tile 16(m) x 128(n), k=64, single product ----
    float sacc[16][4];
#pragma unroll
    for (int ni = 0; ni < 16; ++ni)
#pragma unroll
        for (int e = 0; e < 4; ++e) sacc[ni][e] = 0.0f;

    const uint32_t qb = smb + AQ + (uint32_t)((rw * 16 + lrow8) * (PA * 2));
    const uint32_t kbse = smb + AK + (uint32_t)(lrow8 * (PA * 2));
#pragma unroll
    for (int ks = 0; ks < 4; ++ks) {
        const uint32_t ko = (uint32_t)((ks * 16 + lkoff) * 2);
        uint32_t qf[4];
        ldmx4(qf, qb + ko);
#pragma unroll
        for (int nh = 0; nh < 2; ++nh) {
            uint32_t kf[4][4];
#pragma unroll
            for (int nb8 = 0; nb8 < 4; ++nb8)
                ldmx4(kf[nb8], kbse + (uint32_t)((nh * 64 + nb8 * 16) * (PA * 2)) + ko);
#pragma unroll
            for (int ni = 0; ni < 8; ++ni) {
                const int g = ni >> 1, lo = ni & 1, idx = nh * 8 + ni;
                mma16816(sacc[idx], qf, kf[g][lo], kf[g][lo + 2]);
            }
        }
    }

    // ---- mask + warp-local softmax ----
    if (any_mask) {
#pragma unroll
        for (int ni = 0; ni < 16; ++ni) {
            const uint32_t w = mb[ni >> 2];
            const int b0 = (ni & 3) * 8 + (lane & 3) * 2;
            if ((w >> b0) & 1)       { sacc[ni][0] = -10000.0f; sacc[ni][2] = -10000.0f; }
            if ((w >> (b0 + 1)) & 1) { sacc[ni][1] = -10000.0f; sacc[ni][3] = -10000.0f; }
        }
    }
    float mx0 = -3.0e38f, mx1 = -3.0e38f;
#pragma unroll
    for (int ni = 0; ni < 16; ++ni) {
        mx0 = fmaxf(mx0, fmaxf(sacc[ni][0], sacc[ni][1]));
        mx1 = fmaxf(mx1, fmaxf(sacc[ni][2], sacc[ni][3]));
    }
    mx0 = fmaxf(mx0, __shfl_xor_sync(0xffffffffu, mx0, 1));
    mx0 = fmaxf(mx0, __shfl_xor_sync(0xffffffffu, mx0, 2));
    mx1 = fmaxf(mx1, __shfl_xor_sync(0xffffffffu, mx1, 1));
    mx1 = fmaxf(mx1, __shfl_xor_sync(0xffffffffu, mx1, 2));

    float s0 = 0.0f, s1 = 0.0f;
#pragma unroll
    for (int ni = 0; ni < 16; ++ni) {
        sacc[ni][0] = __expf(sacc[ni][0] - mx0);
        sacc[ni][1] = __expf(sacc[ni][1] - mx0);
        sacc[ni][2] = __expf(sacc[ni][2] - mx1);
        sacc[ni][3] = __expf(sacc[ni][3] - mx1);
        s0 += sacc[ni][0] + sacc[ni][1];
        s1 += sacc[ni][2] + sacc[ni][3];
    }
    s0 += __shfl_xor_sync(0xffffffffu, s0, 1);
    s0 += __shfl_xor_sync(0xffffffffu, s0, 2);
    s1 += __shfl_xor_sync(0xffffffffu, s1, 1);
    s1 += __shfl_xor_sync(0xffffffffu, s1, 2);
    const float inv0 = 1.0f / s0, inv1 = 1.0f / s1;

    // ---- probs (normalized fp32) straight from registers ----
    {
        const int r0 = rw * 16 + (lane >> 2);
        float* pb = probs + (((size_t)h * CDIM + c) * RDIM + r0) * RDIM + (lane & 3) * 2;
#pragma unroll
        for (int ni = 0; ni < 16; ++ni) {
            float2 a; a.x = sacc[ni][0] * inv0; a.y = sacc[ni][1] * inv0;
            float2 b; b.x = sacc[ni][2] * inv1; b.y = sacc[ni][3] * inv1;
            *(float2*)(pb + ni * 8) = a;
            *(float2*)(pb + 8 * RDIM + ni * 8) = b;
        }
    }

    // ---- pack unnormalized P -> fp16 A-fragments ----
    uint32_t ph0[16], ph1[16];
#pragma unroll
    for (int ni = 0; ni < 16; ++ni) {
        ph0[ni] = packh(sacc[ni][0], sacc[ni][1]);
        ph1[ni] = packh(sacc[ni][2], sacc[ni][3]);
    }

    // ---- ctx = P V : warp tile 16(m) x 64(n), k=128, V via ldmatrix.trans ----
    const int trow = (lane & 7) + ((lane >> 4) << 3);
    const int tcol = ((lane >> 3) & 1) * 8;
    const uint32_t vb = smb + AV + (uint32_t)(trow * (PA * 2) + tcol * 2);

    float cacc[8][4];
#pragma unroll
    for (int ni = 0; ni < 8; ++ni)
#pragma unroll
        for (int e = 0; e < 4; ++e) cacc[ni][e] = 0.0f;

#pragma unroll
    for (int kb = 0; kb < 8; ++kb) {
        const uint32_t krow = (uint32_t)(kb * 16 * (PA * 2));
        const uint32_t a_h[4] = { ph0[2 * kb], ph1[2 * kb], ph0[2 * kb + 1], ph1[2 * kb + 1] };
#pragma unroll
        for (int vh2 = 0; vh2 < 2; ++vh2) {
            uint32_t vf[2][4];
#pragma unroll
            for (int nb8 = 0; nb8 < 2; ++nb8)
                ldmx4t(vf[nb8], vb + krow + (uint32_t)((vh2 * 32 + nb8 * 16) * 2));
#pragma unroll
            for (int nl = 0; nl < 4; ++nl) {
                const int g = nl >> 1, lo = nl & 1, idx = vh2 * 4 + nl;
                mma16816(cacc[idx], a_h, vf[g][lo], vf[g][lo + 2]);
            }
        }
    }

    // ---- ctx epilogue: stage in own (consumed) Q rows @144B pitch, then
    //      coalesced 16B global stores (rows are 128B contiguous) ----
    {
        // per-warp staging region: Q rows [16rw, 16rw+16) -> 16 x 144B
        const uint32_t stg = (uint32_t)(AQ + rw * 16 * 144);
        const int r = lane >> 2;           // 0..7
        const int cb = (lane & 3) * 2;     // half-col base
#pragma unroll
        for (int ni = 0; ni < 8; ++ni) {
            const int d = ni * 8 + cb;
            *(__half2*)(sm + stg + r * 144 + d * 2) =
                __half2(__float2half_rn(cacc[ni][0] * inv0),
                        __float2half_rn(cacc[ni][1] * inv0));
            *(__half2*)(sm + stg + (r + 8) * 144 + d * 2) =
                __half2(__float2half_rn(cacc[ni][2] * inv1),
                        __float2half_rn(cacc[ni][3] * inv1));
        }
        __syncwarp();
#pragma unroll
        for (int it = 0; it < 4; ++it) {
            const int idx = lane + it * 32;
            const int r2 = idx >> 3;       // 0..15
            const int cl = idx & 7;        // 16B chunk within 128B row
            const float4 v = *(const float4*)(sm + stg + r2 * 144 + cl * 16);
            const int gi = rw * 16 + r2;
            *(float4*)(g_a + ((size_t)gi * CDIM + c) * EDIM + h * DDIM + cl * 8) = v;
        }
    }
}

// ---------------------------------------------------------------------------
extern "C" void kernel_launch(void* const* d_in, const int* in_sizes, int n_in,
                              void* d_out, int out_size)
{
    const float* x  = (const float*)d_in[0];
    const unsigned char* mask = (const unsigned char*)d_in[2];
    const float* wq = (const float*)d_in[3];
    const float* bq = (const float*)d_in[4];
    const float* wk = (const float*)d_in[5];
    const float* bk = (const float*)d_in[6];
    const float* wv = (const float*)d_in[7];
    const float* bv = (const float*)d_in[8];
    const float* wo = (const float*)d_in[9];
    const float* bo = (const float*)d_in[10];

    float* out   = (float*)d_out;                    // (R, C, 1, E)
    float* probs = out + (size_t)MDIM * EDIM;        // (H, C, 1, R, R)

    const int gemm_smem = 2 * GBUF;                  // 73728
    cudaFuncSetAttribute(gemm_tc, cudaFuncAttributeMaxDynamicSharedMemorySize, gemm_smem);
    cudaFuncSetAttribute(attn_tc, cudaFuncAttributeMaxDynamicSharedMemorySize, ATOT);

    conv_all<<<11520, 1024>>>(x, wq, wk, wv, wo, bq, bk, bv, bo);
    gemm_tc<<<dim3(18, MDIM / 128), 256, gemm_smem>>>(0, 0, out);        // qkv
    attn_tc<<<dim3(CDIM, HDIM), 256, ATOT>>>(mask, probs);
    gemm_tc<<<dim3(6, MDIM / 128), 256, gemm_smem>>>(3 * EDIM, 1, out);  // out proj
}

// round 17
// speedup vs baseline: 1.0548x; 1.0309x over previous
#include <cuda_runtime.h>
#include <cuda_fp16.h>
#include <cstdint>

#define RDIM 128
#define CDIM 384
#define EDIM 768
#define HDIM 12
#define DDIM 64
#define MDIM (RDIM * CDIM)   // 49152

// GEMM tiling: CTA 128x128, 8 warps (2x4), warp tile 64x32, BK=64, double buffer
#define BK 64
#define GP 72                              // fp16/row (144B), conflict-free
#define MTX (128 * GP * 2)                 // 18432 B per matrix tile
#define GBUF (2 * MTX)                     // 36864 (A, B)
#define PS 136                             // epilogue staging pitch (halves)

// attention smem map (bytes): q, k, v each 128x64 fp16 @ pitch PA
#define PA 72      // rows: 144B
#define AQ  0
#define AK  18432
#define AV  36864
#define ABM 55296              /* mask bitmap (4 x u32) */
#define ATOT (ABM + 16)

// ---------------- device scratch (allocation-free rule) ----------------
__device__ __half g_a[(size_t)MDIM * EDIM];      // A (x, then ctx), single fp16
__device__ __half g_w[(size_t)4 * EDIM * EDIM];  // packed wq|wk|wv|wo
__device__ float g_bias[4 * EDIM];
__device__ __half g_q[(size_t)MDIM * EDIM];      // [c][h][i][d]
__device__ __half g_k[(size_t)MDIM * EDIM];
__device__ __half g_v[(size_t)MDIM * EDIM];

// ---------------- helpers ----------------
__device__ __forceinline__ uint32_t smem_to_u32(const void* p) {
    uint32_t a;
    asm("{ .reg .u64 t; cvta.to.shared.u64 t, %1; cvt.u32.u64 %0, t; }"
        : "=r"(a) : "l"(p));
    return a;
}
__device__ __forceinline__ void cp16(uint32_t dst, const void* src) {
    asm volatile("cp.async.cg.shared.global [%0], [%1], 16;"
                 :: "r"(dst), "l"(src) : "memory");
}
__device__ __forceinline__ void cp_commit() {
    asm volatile("cp.async.commit_group;" ::: "memory");
}
__device__ __forceinline__ void cp_wait0() {
    asm volatile("cp.async.wait_group 0;" ::: "memory");
}
__device__ __forceinline__ void ldmx4(uint32_t (&r)[4], uint32_t addr) {
    asm volatile("ldmatrix.sync.aligned.m8n8.x4.shared.b16 {%0,%1,%2,%3}, [%4];"
                 : "=r"(r[0]), "=r"(r[1]), "=r"(r[2]), "=r"(r[3]) : "r"(addr));
}
__device__ __forceinline__ void ldmx4t(uint32_t (&r)[4], uint32_t addr) {
    asm volatile("ldmatrix.sync.aligned.m8n8.x4.trans.shared.b16 {%0,%1,%2,%3}, [%4];"
                 : "=r"(r[0]), "=r"(r[1]), "=r"(r[2]), "=r"(r[3]) : "r"(addr));
}
__device__ __forceinline__ void mma16816(float (&d)[4], const uint32_t (&a)[4],
                                         uint32_t b0, uint32_t b1) {
    asm volatile(
        "mma.sync.aligned.m16n8k16.row.col.f32.f16.f16.f32 "
        "{%0,%1,%2,%3}, {%4,%5,%6,%7}, {%8,%9}, {%0,%1,%2,%3};"
        : "+f"(d[0]), "+f"(d[1]), "+f"(d[2]), "+f"(d[3])
        : "r"(a[0]), "r"(a[1]), "r"(a[2]), "r"(a[3]), "r"(b0), "r"(b1));
}
__device__ __forceinline__ uint32_t packh(float a, float b) {
    __half2 p(__float2half_rn(a), __float2half_rn(b));
    return *(uint32_t*)&p;
}

// ---------------- merged conversion kernel ----------------
// blocks [0, 2304): weights+bias; blocks [2304, 11520): x (float4 granules)
__global__ void conv_all(const float* __restrict__ x,
                         const float* __restrict__ wq, const float* __restrict__ wk,
                         const float* __restrict__ wv, const float* __restrict__ wo,
                         const float* __restrict__ bq, const float* __restrict__ bk,
                         const float* __restrict__ bv, const float* __restrict__ bo)
{
    if (blockIdx.x < 2304) {
        const size_t WSZ = (size_t)EDIM * EDIM;
        size_t i = (size_t)blockIdx.x * blockDim.x + threadIdx.x;  // < 4*WSZ exact
        int sel = (int)(i / WSZ);
        size_t off = i - (size_t)sel * WSZ;
        const float* w = (sel == 0) ? wq : (sel == 1) ? wk : (sel == 2) ? wv : wo;
        g_w[i] = __float2half_rn(w[off]);
        if (i < 4 * EDIM) {
            int s = (int)(i / EDIM), r = (int)(i % EDIM);
            const float* b = (s == 0) ? bq : (s == 1) ? bk : (s == 2) ? bv : bo;
            g_bias[i] = b[r];
        }
    } else {
        int i = (blockIdx.x - 2304) * blockDim.x + threadIdx.x;    // < MDIM*EDIM/4 exact
        float4 v = ((const float4*)x)[i];
        size_t o = (size_t)i * 4;
        *(__half2*)(g_a + o)     = __half2(__float2half_rn(v.x), __float2half_rn(v.y));
        *(__half2*)(g_a + o + 2) = __half2(__float2half_rn(v.z), __float2half_rn(v.w));
    }
}

// ---------------- fp16 HMMA GEMM (single product, BK=64, double buffer) ----------------
__global__ __launch_bounds__(256, 2)
void gemm_tc(int n_off, int mode, float* __restrict__ outp)
{
    extern __shared__ char smdyn[];
    const uint32_t smb = smem_to_u32(smdyn);
    const int t = threadIdx.x;
    const int wid = t >> 5, lane = t & 31;
    const int wm = wid & 1, wn = wid >> 1;           // 2x4 warp grid
    const int bm = blockIdx.y * 128;
    const int nb = n_off + blockIdx.x * 128;

    const __half* srcA = g_a + (size_t)bm * EDIM;
    const __half* srcB = g_w + (size_t)nb * EDIM;

    float acc[4][4][4];
#pragma unroll
    for (int mi = 0; mi < 4; ++mi)
#pragma unroll
        for (int ni = 0; ni < 4; ++ni)
#pragma unroll
            for (int e = 0; e < 4; ++e) acc[mi][ni][e] = 0.0f;

    const int lrow8 = (lane & 7) + ((lane >> 3) & 1) * 8;
    const int lkoff = (lane >> 4) * 8;

    // prefetch chunk 0: per matrix 1024 x 16B; 256 threads x 4
    {
#pragma unroll
        for (int kk = 0; kk < 4; ++kk) {
            const int id = t + kk * 256;
            const int r = id >> 3, cl = id & 7;
            const uint32_t d = smb + (uint32_t)(r * (GP * 2) + cl * 16);
            const int s = r * EDIM + cl * 8;
            cp16(d, srcA + s);
            cp16(d + MTX, srcB + s);
        }
        cp_commit();
    }

    const int NC = EDIM / BK;  // 12
#pragma unroll 1
    for (int ch = 0; ch < NC; ++ch) {
        cp_wait0();
        __syncthreads();
        if (ch + 1 < NC) {
            const uint32_t bufn = ((ch + 1) & 1) * GBUF;
#pragma unroll
            for (int kk = 0; kk < 4; ++kk) {
                const int id = t + kk * 256;
                const int r = id >> 3, cl = id & 7;
                const uint32_t d = smb + bufn + (uint32_t)(r * (GP * 2) + cl * 16);
                const int s = r * EDIM + (ch + 1) * BK + cl * 8;
                cp16(d, srcA + s);
                cp16(d + MTX, srcB + s);
            }
            cp_commit();
        }
        const uint32_t buf = smb + (ch & 1) * GBUF;
        const uint32_t aA = buf + (uint32_t)((wm * 64 + lrow8) * (GP * 2));
        const uint32_t aB = buf + MTX + (uint32_t)((wn * 32 + lrow8) * (GP * 2));
#pragma unroll
        for (int ks = 0; ks < 4; ++ks) {
            const uint32_t kbyte = (uint32_t)((ks * 16 + lkoff) * 2);
            uint32_t bfr[2][4];
#pragma unroll
            for (int ng = 0; ng < 2; ++ng)
                ldmx4(bfr[ng], aB + (uint32_t)(ng * 16 * GP * 2) + kbyte);
#pragma unroll
            for (int mi = 0; mi < 4; ++mi) {
                uint32_t af[4];
                ldmx4(af, aA + (uint32_t)(mi * 16 * GP * 2) + kbyte);
#pragma unroll
                for (int ni = 0; ni < 4; ++ni) {
                    const int ng = ni >> 1, lo = ni & 1;
                    mma16816(acc[mi][ni], af, bfr[ng][lo], bfr[ng][lo + 2]);
                }
            }
        }
    }

    if (mode == 0) {
        // ---- staged epilogue: acc -> smem fp16 tile -> coalesced 16B stores ----
        __syncthreads();   // double buffers dead; reuse as staging
        __half* stg = (__half*)smdyn;
        const int rl = wm * 64 + (lane >> 2);
        const int cl0 = wn * 32 + (lane & 3) * 2;
#pragma unroll
        for (int mi = 0; mi < 4; ++mi) {
#pragma unroll
            for (int half = 0; half < 2; ++half) {
                const int row = rl + mi * 16 + half * 8;
#pragma unroll
                for (int ni = 0; ni < 4; ++ni) {
                    const int col = cl0 + ni * 8;
                    const int ng = nb + col;
                    float ox = acc[mi][ni][half * 2 + 0] + g_bias[ng + 0];
                    float oy = acc[mi][ni][half * 2 + 1] + g_bias[ng + 1];
                    if (ng < EDIM) { ox *= 0.125f; oy *= 0.125f; }
                    *(__half2*)(stg + row * PS + col) =
                        __half2(__float2half_rn(ox), __float2half_rn(oy));
                }
            }
        }
        __syncthreads();
#pragma unroll
        for (int it = 0; it < 8; ++it) {
            const int id = t + it * 256;
            const int row = id >> 4, cl = id & 15;
            const int m = bm + row;
            const int i_ = m / CDIM, c_ = m % CDIM;
            const int ng = nb + cl * 8;
            const int sel = ng / EDIM, f = ng % EDIM, h = f >> 6, d = f & 63;
            __half* dst = (sel == 0) ? g_q : (sel == 1) ? g_k : g_v;
            const float4 v = *(const float4*)(stg + row * PS + cl * 8);
            *(float4*)(dst + (((size_t)c_ * HDIM + h) * RDIM + i_) * DDIM + d) = v;
        }
    } else {
        // out-proj: direct fp32 stores (already full-sector)
        const int r0 = bm + wm * 64 + (lane >> 2);
        const int cbase = nb + wn * 32 + (lane & 3) * 2;
#pragma unroll
        for (int mi = 0; mi < 4; ++mi) {
#pragma unroll
            for (int half = 0; half < 2; ++half) {
                const int m = r0 + mi * 16 + half * 8;
#pragma unroll
                for (int ni = 0; ni < 4; ++ni) {
                    const int ng = cbase + ni * 8;
                    float2 o;
                    o.x = acc[mi][ni][half * 2 + 0] + g_bias[ng + 0];
                    o.y = acc[mi][ni][half * 2 + 1] + g_bias[ng + 1];
                    *(float2*)(outp + (size_t)m * EDIM + (ng - 3 * EDIM)) = o;
                }
            }
        }
    }
}

// ---------------- register-flash fp16 HMMA attention (1 head/CTA, 2 CTAs/SM) ----------------
__global__ __launch_bounds__(256, 2)
void attn_tc(const unsigned char* __restrict__ mask, float* __restrict__ probs)
{
    extern __shared__ char sm[];
    const uint32_t smb = smem_to_u32(sm);
    const int c = blockIdx.x, h = blockIdx.y;
    const int t = threadIdx.x, wid = t >> 5, lane = t & 31;

    // ---- loads: q, k, v, all [128][64] fp16 ----
    {
        const size_t gb = ((size_t)c * HDIM + h) * (RDIM * DDIM);
        const __half* sq[3] = { g_q + gb, g_k + gb, g_v + gb };
        const uint32_t qo[3] = { AQ, AK, AV };
#pragma unroll
        for (int m = 0; m < 3; ++m)
#pragma unroll
            for (int k = 0; k < 4; ++k) {
                const int id = t + k * 256;
                const int r = id >> 3, cl = id & 7;
                cp16(smb + qo[m] + (uint32_t)(r * (PA * 2) + cl * 16),
                     sq[m] + (size_t)r * DDIM + cl * 8);
            }
    }
    cp_commit();

    // mask bitmap
    uint32_t* bmw = (uint32_t*)(sm + ABM);
    if (t < 4) bmw[t] = 0;
    __syncthreads();
    if (t < RDIM && mask[(size_t)t * CDIM + c]) atomicOr(&bmw[t >> 5], 1u << (t & 31));
    cp_wait0();
    __syncthreads();
    const uint32_t mb[4] = { bmw[0], bmw[1], bmw[2], bmw[3] };
    const bool any_mask = (mb[0] | mb[1] | mb[2] | mb[3]) != 0;

    const int rw = wid;                       // warp owns rows [16rw, 16rw+16)
    const int lrow8 = (lane & 7) + ((lane >> 3) & 1) * 8;
    const int lkoff = (lane >> 4) * 8;

    // ---- S = Q K^T : warp tile 16(m) x 128(n), k=64, single product ----
    float sacc[16][4];
#pragma unroll
    for (int ni = 0; ni < 16; ++ni)
#pragma unroll
        for (int e = 0; e < 4; ++e) sacc[ni][e] = 0.0f;

    const uint32_t qb = smb + AQ + (uint32_t)((rw * 16 + lrow8) * (PA * 2));
    const uint32_t kbse = smb + AK + (uint32_t)(lrow8 * (PA * 2));
#pragma unroll
    for (int ks = 0; ks < 4; ++ks) {
        const uint32_t ko = (uint32_t)((ks * 16 + lkoff) * 2);
        uint32_t qf[4];
        ldmx4(qf, qb + ko);
#pragma unroll
        for (int nh = 0; nh < 2; ++nh) {
            uint32_t kf[4][4];
#pragma unroll
            for (int nb8 = 0; nb8 < 4; ++nb8)
                ldmx4(kf[nb8], kbse + (uint32_t)((nh * 64 + nb8 * 16) * (PA * 2)) + ko);
#pragma unroll
            for (int ni = 0; ni < 8; ++ni) {
                const int g = ni >> 1, lo = ni & 1, idx = nh * 8 + ni;
                mma16816(sacc[idx], qf, kf[g][lo], kf[g][lo + 2]);
            }
        }
    }

    // ---- mask + warp-local softmax ----
    if (any_mask) {
#pragma unroll
        for (int ni = 0; ni < 16; ++ni) {
            const uint32_t w = mb[ni >> 2];
            const int b0 = (ni & 3) * 8 + (lane & 3) * 2;
            if ((w >> b0) & 1)       { sacc[ni][0] = -10000.0f; sacc[ni][2] = -10000.0f; }
            if ((w >> (b0 + 1)) & 1) { sacc[ni][1] = -10000.0f; sacc[ni][3] = -10000.0f; }
        }
    }
    float mx0 = -3.0e38f, mx1 = -3.0e38f;
#pragma unroll
    for (int ni = 0; ni < 16; ++ni) {
        mx0 = fmaxf(mx0, fmaxf(sacc[ni][0], sacc[ni][1]));
        mx1 = fmaxf(mx1, fmaxf(sacc[ni][2], sacc[ni][3]));
    }
    mx0 = fmaxf(mx0, __shfl_xor_sync(0xffffffffu, mx0, 1));
    mx0 = fmaxf(mx0, __shfl_xor_sync(0xffffffffu, mx0, 2));
    mx1 = fmaxf(mx1, __shfl_xor_sync(0xffffffffu, mx1, 1));
    mx1 = fmaxf(mx1, __shfl_xor_sync(0xffffffffu, mx1, 2));

    float s0 = 0.0f, s1 = 0.0f;
#pragma unroll
    for (int ni = 0; ni < 16; ++ni) {
        sacc[ni][0] = __expf(sacc[ni][0] - mx0);
        sacc[ni][1] = __expf(sacc[ni][1] - mx0);
        sacc[ni][2] = __expf(sacc[ni][2] - mx1);
        sacc[ni][3] = __expf(sacc[ni][3] - mx1);
        s0 += sacc[ni][0] + sacc[ni][1];
        s1 += sacc[ni][2] + sacc[ni][3];
    }
    s0 += __shfl_xor_sync(0xffffffffu, s0, 1);
    s0 += __shfl_xor_sync(0xffffffffu, s0, 2);
    s1 += __shfl_xor_sync(0xffffffffu, s1, 1);
    s1 += __shfl_xor_sync(0xffffffffu, s1, 2);
    const float inv0 = 1.0f / s0, inv1 = 1.0f / s1;

    // ---- probs (normalized fp32) straight from registers ----
    {
        const int r0 = rw * 16 + (lane >> 2);
        float* pb = probs + (((size_t)h * CDIM + c) * RDIM + r0) * RDIM + (lane & 3) * 2;
#pragma unroll
        for (int ni = 0; ni < 16; ++ni) {
            float2 a; a.x = sacc[ni][0] * inv0; a.y = sacc[ni][1] * inv0;
            float2 b; b.x = sacc[ni][2] * inv1; b.y = sacc[ni][3] * inv1;
            *(float2*)(pb + ni * 8) = a;
            *(float2*)(pb + 8 * RDIM + ni * 8) = b;
        }
    }

    // ---- pack unnormalized P -> fp16 A-fragments ----
    uint32_t ph0[16], ph1[16];
#pragma unroll
    for (int ni = 0; ni < 16; ++ni) {
        ph0[ni] = packh(sacc[ni][0], sacc[ni][1]);
        ph1[ni] = packh(sacc[ni][2], sacc[ni][3]);
    }

    // ---- ctx = P V : warp tile 16(m) x 64(n), k=128, V via ldmatrix.trans ----
    const int trow = (lane & 7) + ((lane >> 4) << 3);
    const int tcol = ((lane >> 3) & 1) * 8;
    const uint32_t vb = smb + AV + (uint32_t)(trow * (PA * 2) + tcol * 2);

    float cacc[8][4];
#pragma unroll
    for (int ni = 0; ni < 8; ++ni)
#pragma unroll
        for (int e = 0; e < 4; ++e) cacc[ni][e] = 0.0f;

#pragma unroll
    for (int kb = 0; kb < 8; ++kb) {
        const uint32_t krow = (uint32_t)(kb * 16 * (PA * 2));
        const uint32_t a_h[4] = { ph0[2 * kb], ph1[2 * kb], ph0[2 * kb + 1], ph1[2 * kb + 1] };
#pragma unroll
        for (int vh2 = 0; vh2 < 2; ++vh2) {
            uint32_t vf[2][4];
#pragma unroll
            for (int nb8 = 0; nb8 < 2; ++nb8)
                ldmx4t(vf[nb8], vb + krow + (uint32_t)((vh2 * 32 + nb8 * 16) * 2));
#pragma unroll
            for (int nl = 0; nl < 4; ++nl) {
                const int g = nl >> 1, lo = nl & 1, idx = vh2 * 4 + nl;
                mma16816(cacc[idx], a_h, vf[g][lo], vf[g][lo + 2]);
            }
        }
    }

    // ---- ctx epilogue: stage in own (consumed) Q rows @144B pitch, then
    //      coalesced 16B global stores (rows are 128B contiguous) ----
    {
        const uint32_t stg = (uint32_t)(AQ + rw * 16 * 144);
        const int r = lane >> 2;           // 0..7
        const int cb = (lane & 3) * 2;     // half-col base
#pragma unroll
        for (int ni = 0; ni < 8; ++ni) {
            const int d = ni * 8 + cb;
            *(__half2*)(sm + stg + r * 144 + d * 2) =
                __half2(__float2half_rn(cacc[ni][0] * inv0),
                        __float2half_rn(cacc[ni][1] * inv0));
            *(__half2*)(sm + stg + (r + 8) * 144 + d * 2) =
                __half2(__float2half_rn(cacc[ni][2] * inv1),
                        __float2half_rn(cacc[ni][3] * inv1));
        }
        __syncwarp();
#pragma unroll
        for (int it = 0; it < 4; ++it) {
            const int idx = lane + it * 32;
            const int r2 = idx >> 3;       // 0..15
            const int cl = idx & 7;        // 16B chunk within 128B row
            const float4 v = *(const float4*)(sm + stg + r2 * 144 + cl * 16);
            const int gi = rw * 16 + r2;
            *(float4*)(g_a + ((size_t)gi * CDIM + c) * EDIM + h * DDIM + cl * 8) = v;
        }
    }
}

// ---------------------------------------------------------------------------
extern "C" void kernel_launch(void* const* d_in, const int* in_sizes, int n_in,
                              void* d_out, int out_size)
{
    const float* x  = (const float*)d_in[0];
    const unsigned char* mask = (const unsigned char*)d_in[2];
    const float* wq = (const float*)d_in[3];
    const float* bq = (const float*)d_in[4];
    const float* wk = (const float*)d_in[5];
    const float* bk = (const float*)d_in[6];
    const float* wv = (const float*)d_in[7];
    const float* bv = (const float*)d_in[8];
    const float* wo = (const float*)d_in[9];
    const float* bo = (const float*)d_in[10];

    float* out   = (float*)d_out;                    // (R, C, 1, E)
    float* probs = out + (size_t)MDIM * EDIM;        // (H, C, 1, R, R)

    const int gemm_smem = 2 * GBUF;                  // 73728
    cudaFuncSetAttribute(gemm_tc, cudaFuncAttributeMaxDynamicSharedMemorySize, gemm_smem);
    cudaFuncSetAttribute(attn_tc, cudaFuncAttributeMaxDynamicSharedMemorySize, ATOT);

    conv_all<<<11520, 1024>>>(x, wq, wk, wv, wo, bq, bk, bv, bo);
    gemm_tc<<<dim3(18, MDIM / 128), 256, gemm_smem>>>(0, 0, out);        // qkv
    attn_tc<<<dim3(CDIM, HDIM), 256, ATOT>>>(mask, probs);
    gemm_tc<<<dim3(6, MDIM / 128), 256, gemm_smem>>>(3 * EDIM, 1, out);  // out proj
}